// round 4
// baseline (speedup 1.0000x reference)
#include <cuda_runtime.h>
#include <cuda_bf16.h>
#include <cstdint>

// ---------------------------------------------------------------------------
// Problem constants
// ---------------------------------------------------------------------------
#define D_DIM 128
#define O_DIM 128
#define R_DIM 4
#define N_MAX 100000

// Scratch: Y laid out [R][N_MAX][O] so each relation's stripe is contiguous.
__device__ float g_Y[(size_t)R_DIM * N_MAX * O_DIM];

// ---------------------------------------------------------------------------
// GEMM tile config: per CTA 256 M-rows x 128 out-cols (one relation).
// 512 threads = 16 warps as 4 (M) x 4 (N); warp tile 64 x 32.
// K = 128 entirely smem-resident. 3 bf16 passes: Ah*Bh + Ah*Bl + Al*Bh.
// ---------------------------------------------------------------------------
#define M_TILE 256

// smem: bf16 tiles, 256-byte row pitch (128 bf16), XOR-swizzled 16B chunks.
#define SM_AH 0
#define SM_AL 65536
#define SM_BH 131072
#define SM_BL 163840
#define SMEM_TOTAL 196608

__device__ __forceinline__ uint32_t smem_u32(const void* p) {
    uint32_t a;
    asm("{ .reg .u64 t; cvta.to.shared.u64 t, %1; cvt.u32.u64 %0, t; }" : "=r"(a) : "l"(p));
    return a;
}

// offset of element (row, k) in a [rows][128] bf16 tile, swizzled
__device__ __forceinline__ uint32_t offAB(int row, int k) {
    return (uint32_t)row * 256u + (uint32_t)(((k >> 3) ^ (row & 7)) * 16) + (uint32_t)((k & 7) * 2);
}

__device__ __forceinline__ void ldsm4(uint32_t* r, uint32_t addr) {
    asm volatile("ldmatrix.sync.aligned.m8n8.x4.shared.b16 {%0,%1,%2,%3}, [%4];"
                 : "=r"(r[0]), "=r"(r[1]), "=r"(r[2]), "=r"(r[3]) : "r"(addr));
}

__device__ __forceinline__ void mma16816(float* c, const uint32_t* a, uint32_t b0, uint32_t b1) {
    asm volatile("mma.sync.aligned.m16n8k16.row.col.f32.bf16.bf16.f32 "
                 "{%0,%1,%2,%3}, {%4,%5,%6,%7}, {%8,%9}, {%0,%1,%2,%3};"
                 : "+f"(c[0]), "+f"(c[1]), "+f"(c[2]), "+f"(c[3])
                 : "r"(a[0]), "r"(a[1]), "r"(a[2]), "r"(a[3]), "r"(b0), "r"(b1));
}

__device__ __forceinline__ void split4(const float4 v, uint2& hi, uint2& lo) {
    __nv_bfloat16 h0 = __float2bfloat16(v.x), h1 = __float2bfloat16(v.y),
                  h2 = __float2bfloat16(v.z), h3 = __float2bfloat16(v.w);
    float l0 = v.x - __bfloat162float(h0), l1 = v.y - __bfloat162float(h1),
          l2 = v.z - __bfloat162float(h2), l3 = v.w - __bfloat162float(h3);
    __nv_bfloat162 ph0 = __nv_bfloat162(h0, h1), ph1 = __nv_bfloat162(h2, h3);
    __nv_bfloat162 pl0 = __floats2bfloat162_rn(l0, l1), pl1 = __floats2bfloat162_rn(l2, l3);
    hi.x = *reinterpret_cast<uint32_t*>(&ph0);
    hi.y = *reinterpret_cast<uint32_t*>(&ph1);
    lo.x = *reinterpret_cast<uint32_t*>(&pl0);
    lo.y = *reinterpret_cast<uint32_t*>(&pl1);
}

__global__ void __launch_bounds__(512, 1)
gemm_mma(const float* __restrict__ x, const float* __restrict__ W, int N)
{
    extern __shared__ char smem[];
    const uint32_t sb = smem_u32(smem);
    const int tid    = threadIdx.x;
    const int lane   = tid & 31;
    const int wid    = tid >> 5;
    const int warp_m = wid >> 2;          // 0..3
    const int warp_n = wid & 3;           // 0..3
    const int r      = blockIdx.y;        // relation
    const int m0     = blockIdx.x * M_TILE;

    // ---- load A: x[m0 .. m0+256) x [0,128) -> hi/lo bf16 tiles ----
#pragma unroll
    for (int i = 0; i < 16; i++) {
        int idx = tid + i * 512;          // 8192 float4 tasks
        int row = idx >> 5;
        int f4  = idx & 31;
        int gm  = m0 + row;
        float4 v = make_float4(0.f, 0.f, 0.f, 0.f);
        if (gm < N) v = *reinterpret_cast<const float4*>(x + (size_t)gm * D_DIM + f4 * 4);
        uint2 hi, lo;
        split4(v, hi, lo);
        uint32_t off = offAB(row, f4 * 4);
        *reinterpret_cast<uint2*>(smem + SM_AH + off) = hi;
        *reinterpret_cast<uint2*>(smem + SM_AL + off) = lo;
    }

    // ---- load B (transposed): B[o][d] = W[r*128+d][o] ----
    {
        const float* Wb = W + (size_t)r * D_DIM * O_DIM;
#pragma unroll
        for (int i = 0; i < 8; i++) {
            int idx = tid + i * 512;      // 4096 float4 tasks
            int d  = idx >> 5;            // W row within block
            int oq = idx & 31;
            float4 v = *reinterpret_cast<const float4*>(Wb + (size_t)d * O_DIM + oq * 4);
            float vv[4] = {v.x, v.y, v.z, v.w};
#pragma unroll
            for (int j = 0; j < 4; j++) {
                int o = oq * 4 + j;
                __nv_bfloat16 h = __float2bfloat16(vv[j]);
                __nv_bfloat16 l = __float2bfloat16(vv[j] - __bfloat162float(h));
                uint32_t off = offAB(o, d);
                *reinterpret_cast<__nv_bfloat16*>(smem + SM_BH + off) = h;
                *reinterpret_cast<__nv_bfloat16*>(smem + SM_BL + off) = l;
            }
        }
    }
    __syncthreads();

    // ---- MMA mainloop ----
    float acc[4][4][4];
#pragma unroll
    for (int mt = 0; mt < 4; mt++)
#pragma unroll
        for (int nt = 0; nt < 4; nt++)
#pragma unroll
            for (int q = 0; q < 4; q++) acc[mt][nt][q] = 0.f;

    const int a_row = warp_m * 64 + (lane & 15);
    const int b_row = warp_n * 32 + (lane & 15);
    const int khalf = (lane >> 4) * 8;

#pragma unroll
    for (int pass = 0; pass < 3; pass++) {
        const uint32_t As = sb + (pass == 2 ? SM_AL : SM_AH);
        const uint32_t Bs = sb + (pass == 1 ? SM_BL : SM_BH);
#pragma unroll
        for (int ks = 0; ks < 8; ks++) {
            const int k0 = ks * 16;
            uint32_t a[4][4], b[2][4];
#pragma unroll
            for (int mt = 0; mt < 4; mt++)
                ldsm4(a[mt], As + offAB(a_row + mt * 16, k0 + khalf));
#pragma unroll
            for (int np = 0; np < 2; np++)
                ldsm4(b[np], Bs + offAB(b_row + np * 16, k0 + khalf));
#pragma unroll
            for (int mt = 0; mt < 4; mt++) {
#pragma unroll
                for (int nt = 0; nt < 4; nt++) {
                    const uint32_t* bb = b[nt >> 1];
                    uint32_t b0 = (nt & 1) ? bb[1] : bb[0];
                    uint32_t b1 = (nt & 1) ? bb[3] : bb[2];
                    mma16816(acc[mt][nt], a[mt], b0, b1);
                }
            }
        }
    }

    // ---- epilogue: direct float2 stores to Y[r] ----
    float* Yr = g_Y + (size_t)r * N_MAX * O_DIM;
#pragma unroll
    for (int mt = 0; mt < 4; mt++) {
        int gm0 = m0 + warp_m * 64 + mt * 16 + (lane >> 2);
#pragma unroll
        for (int nt = 0; nt < 4; nt++) {
            int o = warp_n * 32 + nt * 8 + (lane & 3) * 2;
            if (gm0 < N)
                *reinterpret_cast<float2*>(Yr + (size_t)gm0 * O_DIM + o) =
                    make_float2(acc[mt][nt][0], acc[mt][nt][1]);
            if (gm0 + 8 < N)
                *reinterpret_cast<float2*>(Yr + (size_t)(gm0 + 8) * O_DIM + o) =
                    make_float2(acc[mt][nt][2], acc[mt][nt][3]);
        }
    }
}

// ---------------------------------------------------------------------------
// Scatter: out[row,:] += val * Y_r[col,:]   (red.global.add.v4.f32)
// ---------------------------------------------------------------------------
__global__ __launch_bounds__(256)
void scatter_kernel(const int* __restrict__ rows, const int* __restrict__ cols,
                    const float* __restrict__ vals, float* __restrict__ out,
                    int E)
{
    const int r    = blockIdx.y;
    const int lane = threadIdx.x & 31;
    const int warp = (blockIdx.x * blockDim.x + threadIdx.x) >> 5;
    const int nwarps = (gridDim.x * blockDim.x) >> 5;

    const int*   __restrict__ rr = rows + (size_t)r * E;
    const int*   __restrict__ cc = cols + (size_t)r * E;
    const float* __restrict__ vv = vals + (size_t)r * E;
    const float* __restrict__ Yr = g_Y + (size_t)r * N_MAX * O_DIM;

    for (int e = warp; e < E; e += nwarps) {
        int   row = __ldg(rr + e);
        int   col = __ldg(cc + e);
        float v   = __ldg(vv + e);

        float4 p = *(const float4*)(Yr + (size_t)col * O_DIM + lane * 4);
        p.x *= v; p.y *= v; p.z *= v; p.w *= v;

        float* dst = out + (size_t)row * O_DIM + lane * 4;
        asm volatile("red.global.add.v4.f32 [%0], {%1, %2, %3, %4};"
                     :: "l"(dst), "f"(p.x), "f"(p.y), "f"(p.z), "f"(p.w)
                     : "memory");
    }
}

// ---------------------------------------------------------------------------
// kernel_launch
// ---------------------------------------------------------------------------
extern "C" void kernel_launch(void* const* d_in, const int* in_sizes, int n_in,
                              void* d_out, int out_size)
{
    const float* x        = (const float*)d_in[0];
    const int*   edge_row = (const int*)  d_in[1];
    const int*   edge_col = (const int*)  d_in[2];
    const float* edge_val = (const float*)d_in[3];
    const float* W        = (const float*)d_in[4];
    float*       out      = (float*)d_out;

    const int N = in_sizes[0] / D_DIM;          // 100000
    const int E = in_sizes[1] / R_DIM;          // 400000

    cudaFuncSetAttribute(gemm_mma, cudaFuncAttributeMaxDynamicSharedMemorySize, SMEM_TOTAL);

    cudaMemsetAsync(out, 0, (size_t)out_size * sizeof(float), 0);

    {
        dim3 grid((N + M_TILE - 1) / M_TILE, R_DIM);
        gemm_mma<<<grid, 512, SMEM_TOTAL>>>(x, W, N);
    }
    {
        dim3 grid(1024, R_DIM);
        scatter_kernel<<<grid, 256>>>(edge_row, edge_col, edge_val, out, E);
    }
}

// round 5
// speedup vs baseline: 1.5549x; 1.5549x over previous
#include <cuda_runtime.h>
#include <cuda_fp16.h>
#include <cstdint>

// ---------------------------------------------------------------------------
// Problem constants
// ---------------------------------------------------------------------------
#define D_DIM 128
#define O_DIM 128
#define R_DIM 4
#define N_MAX 100000

// Scratch: Y in fp16, laid out [R][N_MAX][O] (102.4 MB)
__device__ __half g_Yh[(size_t)R_DIM * N_MAX * O_DIM];

// ---------------------------------------------------------------------------
// GEMM: per CTA 128 M-rows x 128 out-cols (one relation). 256 threads =
// 8 warps as 2(M) x 4(N); warp tile 64x32. K=128 smem-resident, fp16 1-pass.
// ---------------------------------------------------------------------------
#define SM_A 0
#define SM_B 32768
#define SMEM_TOTAL 65536

__device__ __forceinline__ uint32_t smem_u32(const void* p) {
    uint32_t a;
    asm("{ .reg .u64 t; cvta.to.shared.u64 t, %1; cvt.u32.u64 %0, t; }" : "=r"(a) : "l"(p));
    return a;
}

// offset of element (row, k) in a [rows][128] fp16 tile, 256B pitch, swizzled
__device__ __forceinline__ uint32_t offAB(int row, int k) {
    return (uint32_t)row * 256u + (uint32_t)(((k >> 3) ^ (row & 7)) * 16) + (uint32_t)((k & 7) * 2);
}

__device__ __forceinline__ void ldsm4(uint32_t* r, uint32_t addr) {
    asm volatile("ldmatrix.sync.aligned.m8n8.x4.shared.b16 {%0,%1,%2,%3}, [%4];"
                 : "=r"(r[0]), "=r"(r[1]), "=r"(r[2]), "=r"(r[3]) : "r"(addr));
}

__device__ __forceinline__ void mma16816(float* c, const uint32_t* a, uint32_t b0, uint32_t b1) {
    asm volatile("mma.sync.aligned.m16n8k16.row.col.f32.f16.f16.f32 "
                 "{%0,%1,%2,%3}, {%4,%5,%6,%7}, {%8,%9}, {%0,%1,%2,%3};"
                 : "+f"(c[0]), "+f"(c[1]), "+f"(c[2]), "+f"(c[3])
                 : "r"(a[0]), "r"(a[1]), "r"(a[2]), "r"(a[3]), "r"(b0), "r"(b1));
}

__global__ void __launch_bounds__(256, 2)
gemm_fp16(const float* __restrict__ x, const float* __restrict__ W, int N)
{
    extern __shared__ char smem[];
    const uint32_t sb = smem_u32(smem);
    const int tid    = threadIdx.x;
    const int lane   = tid & 31;
    const int wid    = tid >> 5;
    const int warp_m = wid >> 2;          // 0..1
    const int warp_n = wid & 3;           // 0..3
    const int r      = blockIdx.x;        // relation fastest -> x tile L2 reuse
    const int m0     = blockIdx.y * 128;

    // ---- load A: x[m0..m0+128) x [0,128) -> fp16 smem ----
#pragma unroll
    for (int i = 0; i < 16; i++) {
        int idx = tid + i * 256;          // 4096 float4 tasks
        int row = idx >> 5;
        int f4  = idx & 31;
        int gm  = m0 + row;
        float4 v = make_float4(0.f, 0.f, 0.f, 0.f);
        if (gm < N) v = *reinterpret_cast<const float4*>(x + (size_t)gm * D_DIM + f4 * 4);
        __half2 h01 = __floats2half2_rn(v.x, v.y);
        __half2 h23 = __floats2half2_rn(v.z, v.w);
        uint2 pk = make_uint2(*reinterpret_cast<uint32_t*>(&h01),
                              *reinterpret_cast<uint32_t*>(&h23));
        *reinterpret_cast<uint2*>(smem + SM_A + offAB(row, f4 * 4)) = pk;
    }

    // ---- load B (transposed): B[o][d] = W[r*128+d][o], fp16 ----
    {
        const float* Wb = W + (size_t)r * D_DIM * O_DIM;
#pragma unroll
        for (int i = 0; i < 16; i++) {
            int idx = tid + i * 256;      // 4096 float4 tasks
            int d  = idx >> 5;
            int oq = idx & 31;
            float4 v = *reinterpret_cast<const float4*>(Wb + (size_t)d * O_DIM + oq * 4);
            float vv[4] = {v.x, v.y, v.z, v.w};
#pragma unroll
            for (int j = 0; j < 4; j++) {
                int o = oq * 4 + j;
                *reinterpret_cast<__half*>(smem + SM_B + offAB(o, d)) = __float2half_rn(vv[j]);
            }
        }
    }
    __syncthreads();

    // ---- MMA mainloop (single fp16 pass, K=128) ----
    float acc[4][4][4];
#pragma unroll
    for (int mt = 0; mt < 4; mt++)
#pragma unroll
        for (int nt = 0; nt < 4; nt++)
#pragma unroll
            for (int q = 0; q < 4; q++) acc[mt][nt][q] = 0.f;

    const int a_row = warp_m * 64 + (lane & 15);
    const int b_row = warp_n * 32 + (lane & 15);
    const int khalf = (lane >> 4) * 8;
    const uint32_t As = sb + SM_A, Bs = sb + SM_B;

#pragma unroll
    for (int ks = 0; ks < 8; ks++) {
        const int k0 = ks * 16;
        uint32_t a[4][4], b[2][4];
#pragma unroll
        for (int mt = 0; mt < 4; mt++)
            ldsm4(a[mt], As + offAB(a_row + mt * 16, k0 + khalf));
#pragma unroll
        for (int np = 0; np < 2; np++)
            ldsm4(b[np], Bs + offAB(b_row + np * 16, k0 + khalf));
#pragma unroll
        for (int mt = 0; mt < 4; mt++) {
#pragma unroll
            for (int nt = 0; nt < 4; nt++) {
                const uint32_t* bb = b[nt >> 1];
                uint32_t b0 = (nt & 1) ? bb[1] : bb[0];
                uint32_t b1 = (nt & 1) ? bb[3] : bb[2];
                mma16816(acc[mt][nt], a[mt], b0, b1);
            }
        }
    }

    // ---- epilogue: fp16 stores to Y ----
    __half* Yr = g_Yh + (size_t)r * N_MAX * O_DIM;
#pragma unroll
    for (int mt = 0; mt < 4; mt++) {
        int gm0 = m0 + warp_m * 64 + mt * 16 + (lane >> 2);
#pragma unroll
        for (int nt = 0; nt < 4; nt++) {
            int o = warp_n * 32 + nt * 8 + (lane & 3) * 2;
            if (gm0 < N) {
                __half2 h = __floats2half2_rn(acc[mt][nt][0], acc[mt][nt][1]);
                *reinterpret_cast<uint32_t*>(Yr + (size_t)gm0 * O_DIM + o) =
                    *reinterpret_cast<uint32_t*>(&h);
            }
            if (gm0 + 8 < N) {
                __half2 h = __floats2half2_rn(acc[mt][nt][2], acc[mt][nt][3]);
                *reinterpret_cast<uint32_t*>(Yr + (size_t)(gm0 + 8) * O_DIM + o) =
                    *reinterpret_cast<uint32_t*>(&h);
            }
        }
    }
}

// ---------------------------------------------------------------------------
// Scatter: out[row,:] += val * Y_r[col,:]
// Per edge: 32 lanes x (uint2 fp16 gather = 8B) + (red.v4.f32 = 16B)
// ---------------------------------------------------------------------------
__global__ __launch_bounds__(256)
void scatter_kernel(const int* __restrict__ rows, const int* __restrict__ cols,
                    const float* __restrict__ vals, float* __restrict__ out,
                    int E)
{
    const int r    = blockIdx.y;
    const int lane = threadIdx.x & 31;
    const int warp = (blockIdx.x * blockDim.x + threadIdx.x) >> 5;
    const int nwarps = (gridDim.x * blockDim.x) >> 5;

    const int*   __restrict__ rr = rows + (size_t)r * E;
    const int*   __restrict__ cc = cols + (size_t)r * E;
    const float* __restrict__ vv = vals + (size_t)r * E;
    const __half* __restrict__ Yr = g_Yh + (size_t)r * N_MAX * O_DIM;

    for (int e = warp; e < E; e += nwarps) {
        int   row = __ldg(rr + e);
        int   col = __ldg(cc + e);
        float v   = __ldg(vv + e);

        uint2 q = *reinterpret_cast<const uint2*>(Yr + (size_t)col * O_DIM + lane * 4);
        __half2 h0 = *reinterpret_cast<__half2*>(&q.x);
        __half2 h1 = *reinterpret_cast<__half2*>(&q.y);
        float2 f0 = __half22float2(h0);
        float2 f1 = __half22float2(h1);

        float* dst = out + (size_t)row * O_DIM + lane * 4;
        asm volatile("red.global.add.v4.f32 [%0], {%1, %2, %3, %4};"
                     :: "l"(dst), "f"(f0.x * v), "f"(f0.y * v), "f"(f1.x * v), "f"(f1.y * v)
                     : "memory");
    }
}

// ---------------------------------------------------------------------------
// kernel_launch
// ---------------------------------------------------------------------------
extern "C" void kernel_launch(void* const* d_in, const int* in_sizes, int n_in,
                              void* d_out, int out_size)
{
    const float* x        = (const float*)d_in[0];
    const int*   edge_row = (const int*)  d_in[1];
    const int*   edge_col = (const int*)  d_in[2];
    const float* edge_val = (const float*)d_in[3];
    const float* W        = (const float*)d_in[4];
    float*       out      = (float*)d_out;

    const int N = in_sizes[0] / D_DIM;          // 100000
    const int E = in_sizes[1] / R_DIM;          // 400000

    cudaFuncSetAttribute(gemm_fp16, cudaFuncAttributeMaxDynamicSharedMemorySize, SMEM_TOTAL);

    cudaMemsetAsync(out, 0, (size_t)out_size * sizeof(float), 0);

    {
        dim3 grid(R_DIM, (N + 127) / 128);      // relation fastest -> x L2 reuse
        gemm_fp16<<<grid, 256, SMEM_TOTAL>>>(x, W, N);
    }
    {
        dim3 grid(1024, R_DIM);
        scatter_kernel<<<grid, 256>>>(edge_row, edge_col, edge_val, out, E);
    }
}

// round 7
// speedup vs baseline: 2.0563x; 1.3225x over previous
#include <cuda_runtime.h>
#include <cuda_fp16.h>
#include <cstdint>

// ---------------------------------------------------------------------------
// Problem constants
// ---------------------------------------------------------------------------
#define D_DIM 128
#define O_DIM 128
#define R_DIM 4
#define N_MAX 100000

// Scratch
__device__ __half g_Yh[(size_t)R_DIM * N_MAX * O_DIM];   // Y fp16 [R][N][O]
__device__ __half g_xh[(size_t)N_MAX * D_DIM];           // x fp16 [N][D]
__device__ __half g_WhT[(size_t)R_DIM * O_DIM * D_DIM];  // W^T fp16 [R][O][D]

// ---------------------------------------------------------------------------
// Pre-pass: x -> fp16
// ---------------------------------------------------------------------------
__global__ void __launch_bounds__(256)
convert_x(const float* __restrict__ x, int N)
{
    int idx = blockIdx.x * blockDim.x + threadIdx.x;   // one float4 -> half4
    int total = N * (D_DIM / 4);
    if (idx >= total) return;
    float4 v = *reinterpret_cast<const float4*>(x + (size_t)idx * 4);
    __half2 h01 = __floats2half2_rn(v.x, v.y);
    __half2 h23 = __floats2half2_rn(v.z, v.w);
    uint2 pk = make_uint2(*reinterpret_cast<uint32_t*>(&h01),
                          *reinterpret_cast<uint32_t*>(&h23));
    *reinterpret_cast<uint2*>(g_xh + (size_t)idx * 4) = pk;
}

// Pre-pass: W[r*128+d][o] -> WhT[r][o][d], fp16, smem tile transpose
__global__ void __launch_bounds__(1024)
convert_Wt(const float* __restrict__ W)
{
    __shared__ float s[32][33];
    const int r  = blockIdx.y;
    const int td = (blockIdx.x >> 2) * 32;   // d-tile base
    const int to = (blockIdx.x & 3) * 32;    // o-tile base
    const int tx = threadIdx.x & 31;
    const int ty = threadIdx.x >> 5;
    s[ty][tx] = W[(size_t)(r * D_DIM + td + ty) * O_DIM + to + tx];
    __syncthreads();
    g_WhT[(size_t)r * O_DIM * D_DIM + (size_t)(to + ty) * D_DIM + td + tx] =
        __float2half_rn(s[tx][ty]);
}

// ---------------------------------------------------------------------------
// GEMM: per CTA 128 M-rows x 128 out-cols (one relation). 256 threads =
// 8 warps as 2(M) x 4(N); warp tile 64x32. K=128 smem-resident, fp16.
// ---------------------------------------------------------------------------
#define SM_A 0
#define SM_B 32768
#define SMEM_TOTAL 65536

__device__ __forceinline__ uint32_t smem_u32(const void* p) {
    uint32_t a;
    asm("{ .reg .u64 t; cvta.to.shared.u64 t, %1; cvt.u32.u64 %0, t; }" : "=r"(a) : "l"(p));
    return a;
}

// offset of element (row, k) in a [rows][128] fp16 tile, 256B pitch, swizzled
__device__ __forceinline__ uint32_t offAB(int row, int k) {
    return (uint32_t)row * 256u + (uint32_t)(((k >> 3) ^ (row & 7)) * 16) + (uint32_t)((k & 7) * 2);
}

__device__ __forceinline__ void ldsm4(uint32_t* r, uint32_t addr) {
    asm volatile("ldmatrix.sync.aligned.m8n8.x4.shared.b16 {%0,%1,%2,%3}, [%4];"
                 : "=r"(r[0]), "=r"(r[1]), "=r"(r[2]), "=r"(r[3]) : "r"(addr));
}

__device__ __forceinline__ void mma16816(float* c, const uint32_t* a, uint32_t b0, uint32_t b1) {
    asm volatile("mma.sync.aligned.m16n8k16.row.col.f32.f16.f16.f32 "
                 "{%0,%1,%2,%3}, {%4,%5,%6,%7}, {%8,%9}, {%0,%1,%2,%3};"
                 : "+f"(c[0]), "+f"(c[1]), "+f"(c[2]), "+f"(c[3])
                 : "r"(a[0]), "r"(a[1]), "r"(a[2]), "r"(a[3]), "r"(b0), "r"(b1));
}

__global__ void __launch_bounds__(256, 2)
gemm_fp16(int N)
{
    extern __shared__ char smem[];
    const uint32_t sb = smem_u32(smem);
    const int tid    = threadIdx.x;
    const int lane   = tid & 31;
    const int wid    = tid >> 5;
    const int warp_m = wid >> 2;          // 0..1
    const int warp_n = wid & 3;           // 0..3
    const int r      = blockIdx.x;        // relation fastest -> x L2 reuse
    const int m0     = blockIdx.y * 128;

    // ---- fill A (x_h tile) and B (WhT[r]) via LDG.128 -> swizzled STS.128 ----
    // Padding rows (gm >= N) load row N-1: harmless, Y rows >= N never read.
    {
        const __half* Wt = g_WhT + (size_t)r * O_DIM * D_DIM;
#pragma unroll
        for (int i = 0; i < 8; i++) {
            int t   = tid + i * 256;      // 2048 tasks, one 16B chunk each
            int row = t >> 4;
            int c   = t & 15;
            uint32_t dsw = (uint32_t)row * 256u + (uint32_t)((c ^ (row & 7)) * 16);
            int gm  = m0 + row;
            int gmc = (gm < N) ? gm : (N - 1);
            uint4 va = *reinterpret_cast<const uint4*>(g_xh + (size_t)gmc * D_DIM + c * 8);
            uint4 vb = *reinterpret_cast<const uint4*>(Wt + (size_t)row * D_DIM + c * 8);
            *reinterpret_cast<uint4*>(smem + SM_A + dsw) = va;
            *reinterpret_cast<uint4*>(smem + SM_B + dsw) = vb;
        }
    }
    __syncthreads();

    // ---- MMA mainloop (single fp16 pass, K=128) ----
    float acc[4][4][4];
#pragma unroll
    for (int mt = 0; mt < 4; mt++)
#pragma unroll
        for (int nt = 0; nt < 4; nt++)
#pragma unroll
            for (int q = 0; q < 4; q++) acc[mt][nt][q] = 0.f;

    const int a_row = warp_m * 64 + (lane & 15);
    const int b_row = warp_n * 32 + (lane & 15);
    const int khalf = (lane >> 4) * 8;
    const uint32_t As = sb + SM_A, Bs = sb + SM_B;

#pragma unroll
    for (int ks = 0; ks < 8; ks++) {
        const int k0 = ks * 16;
        uint32_t a[4][4], b[2][4];
#pragma unroll
        for (int mt = 0; mt < 4; mt++)
            ldsm4(a[mt], As + offAB(a_row + mt * 16, k0 + khalf));
#pragma unroll
        for (int np = 0; np < 2; np++)
            ldsm4(b[np], Bs + offAB(b_row + np * 16, k0 + khalf));
#pragma unroll
        for (int mt = 0; mt < 4; mt++) {
#pragma unroll
            for (int nt = 0; nt < 4; nt++) {
                const uint32_t* bb = b[nt >> 1];
                uint32_t b0 = (nt & 1) ? bb[1] : bb[0];
                uint32_t b1 = (nt & 1) ? bb[3] : bb[2];
                mma16816(acc[mt][nt], a[mt], b0, b1);
            }
        }
    }

    // ---- epilogue: fp16 stores to Y ----
    __half* Yr = g_Yh + (size_t)r * N_MAX * O_DIM;
#pragma unroll
    for (int mt = 0; mt < 4; mt++) {
        int gm0 = m0 + warp_m * 64 + mt * 16 + (lane >> 2);
#pragma unroll
        for (int nt = 0; nt < 4; nt++) {
            int o = warp_n * 32 + nt * 8 + (lane & 3) * 2;
            if (gm0 < N) {
                __half2 h = __floats2half2_rn(acc[mt][nt][0], acc[mt][nt][1]);
                *reinterpret_cast<uint32_t*>(Yr + (size_t)gm0 * O_DIM + o) =
                    *reinterpret_cast<uint32_t*>(&h);
            }
            if (gm0 + 8 < N) {
                __half2 h = __floats2half2_rn(acc[mt][nt][2], acc[mt][nt][3]);
                *reinterpret_cast<uint32_t*>(Yr + (size_t)(gm0 + 8) * O_DIM + o) =
                    *reinterpret_cast<uint32_t*>(&h);
            }
        }
    }
}

// ---------------------------------------------------------------------------
// Scatter: out[row,:] += val * Y_r[col,:]
// ---------------------------------------------------------------------------
__global__ __launch_bounds__(256)
void scatter_kernel(const int* __restrict__ rows, const int* __restrict__ cols,
                    const float* __restrict__ vals, float* __restrict__ out,
                    int E)
{
    const int r    = blockIdx.y;
    const int lane = threadIdx.x & 31;
    const int warp = (blockIdx.x * blockDim.x + threadIdx.x) >> 5;
    const int nwarps = (gridDim.x * blockDim.x) >> 5;

    const int*   __restrict__ rr = rows + (size_t)r * E;
    const int*   __restrict__ cc = cols + (size_t)r * E;
    const float* __restrict__ vv = vals + (size_t)r * E;
    const __half* __restrict__ Yr = g_Yh + (size_t)r * N_MAX * O_DIM;

    for (int e = warp; e < E; e += nwarps) {
        int   row = __ldg(rr + e);
        int   col = __ldg(cc + e);
        float v   = __ldg(vv + e);

        uint2 q = *reinterpret_cast<const uint2*>(Yr + (size_t)col * O_DIM + lane * 4);
        __half2 h0 = *reinterpret_cast<__half2*>(&q.x);
        __half2 h1 = *reinterpret_cast<__half2*>(&q.y);
        float2 f0 = __half22float2(h0);
        float2 f1 = __half22float2(h1);

        float* dst = out + (size_t)row * O_DIM + lane * 4;
        asm volatile("red.global.add.v4.f32 [%0], {%1, %2, %3, %4};"
                     :: "l"(dst), "f"(f0.x * v), "f"(f0.y * v), "f"(f1.x * v), "f"(f1.y * v)
                     : "memory");
    }
}

// ---------------------------------------------------------------------------
// kernel_launch
// ---------------------------------------------------------------------------
extern "C" void kernel_launch(void* const* d_in, const int* in_sizes, int n_in,
                              void* d_out, int out_size)
{
    const float* x        = (const float*)d_in[0];
    const int*   edge_row = (const int*)  d_in[1];
    const int*   edge_col = (const int*)  d_in[2];
    const float* edge_val = (const float*)d_in[3];
    const float* W        = (const float*)d_in[4];
    float*       out      = (float*)d_out;

    const int N = in_sizes[0] / D_DIM;          // 100000
    const int E = in_sizes[1] / R_DIM;          // 400000

    cudaFuncSetAttribute(gemm_fp16, cudaFuncAttributeMaxDynamicSharedMemorySize, SMEM_TOTAL);

    cudaMemsetAsync(out, 0, (size_t)out_size * sizeof(float), 0);

    // Pre-pass conversions
    {
        int total = N * (D_DIM / 4);
        convert_x<<<(total + 255) / 256, 256>>>(x, N);
        dim3 gw(16, R_DIM);
        convert_Wt<<<gw, 1024>>>(W);
    }
    // GEMM
    {
        dim3 grid(R_DIM, (N + 127) / 128);      // relation fastest -> x L2 reuse
        gemm_fp16<<<grid, 256, SMEM_TOTAL>>>(N);
    }
    // Scatter
    {
        dim3 grid(1024, R_DIM);
        scatter_kernel<<<grid, 256>>>(edge_row, edge_col, edge_val, out, E);
    }
}